// round 1
// baseline (speedup 1.0000x reference)
#include <cuda_runtime.h>

#define DD 2048
#define BB 256
#define TT 64

// scratch: u[b,d] = (E @ W)[b,d] + hb[d]   (2 MB, static device array — no allocs)
__device__ float g_u[BB * DD];

// ---------------------------------------------------------------------------
// Kernel A: tiled fp32 GEMM  U = E @ W + hb
//   E: [256, 2048] row-major, W: [2048, 2048] row-major
//   BM=BN=64, BK=32, 256 threads, 4x4 micro-tile per thread
// ---------------------------------------------------------------------------
__global__ __launch_bounds__(256) void gemm_u_kernel(
    const float* __restrict__ E,
    const float* __restrict__ W,
    const float* __restrict__ hb)
{
    constexpr int BM = 64, BN = 64, BK = 32;
    __shared__ float As[BK][BM + 4];   // transposed A tile, padded vs bank conflicts
    __shared__ float Bs[BK][BN];

    const int bm  = blockIdx.y * BM;
    const int bn  = blockIdx.x * BN;
    const int tid = threadIdx.x;
    const int tx  = tid & 15;          // 16 thread cols
    const int ty  = tid >> 4;          // 16 thread rows

    float acc[4][4] = {};

    for (int k0 = 0; k0 < DD; k0 += BK) {
        // load A tile (64 rows x 32 k) as float4, store transposed
        #pragma unroll
        for (int r = 0; r < 2; r++) {
            int l   = tid + 256 * r;        // float4 index (512 total)
            int row = l >> 3;               // 8 float4 per row
            int kk  = (l & 7) << 2;
            float4 v = *reinterpret_cast<const float4*>(&E[(bm + row) * DD + k0 + kk]);
            As[kk + 0][row] = v.x;
            As[kk + 1][row] = v.y;
            As[kk + 2][row] = v.z;
            As[kk + 3][row] = v.w;
        }
        // load B tile (32 k x 64 cols) as float4, coalesced
        #pragma unroll
        for (int r = 0; r < 2; r++) {
            int l   = tid + 256 * r;
            int row = l >> 4;               // 16 float4 per row
            int cc  = (l & 15) << 2;
            *reinterpret_cast<float4*>(&Bs[row][cc]) =
                *reinterpret_cast<const float4*>(&W[(k0 + row) * DD + bn + cc]);
        }
        __syncthreads();

        #pragma unroll
        for (int k = 0; k < BK; k++) {
            float a[4], b[4];
            #pragma unroll
            for (int i = 0; i < 4; i++) a[i] = As[k][ty * 4 + i];
            #pragma unroll
            for (int j = 0; j < 4; j++) b[j] = Bs[k][tx * 4 + j];
            #pragma unroll
            for (int i = 0; i < 4; i++)
                #pragma unroll
                for (int j = 0; j < 4; j++)
                    acc[i][j] = fmaf(a[i], b[j], acc[i][j]);
        }
        __syncthreads();
    }

    #pragma unroll
    for (int i = 0; i < 4; i++) {
        int row = bm + ty * 4 + i;
        #pragma unroll
        for (int j = 0; j < 4; j++) {
            int col = bn + tx * 4 + j;
            g_u[row * DD + col] = acc[i][j] + hb[col];
        }
    }
}

// ---------------------------------------------------------------------------
// Kernel B: per-batch scoring. One CTA per b (256 CTAs, 256 threads).
//   vb_b    = dot(E[b], vb)
//   pos     = dot(u[b], cand[b]) + vb_b        (candidate@hb cancels!)
//   neg[t]  = dot(theo[b,t], u[b]) + vb_b
//   out[b, 0] = pos ; out[b, 1+t] = neg[t]
// ---------------------------------------------------------------------------
__global__ __launch_bounds__(256) void score_kernel(
    const float* __restrict__ E,
    const float* __restrict__ theo,
    const float* __restrict__ cand,
    const float* __restrict__ vb,
    float* __restrict__ out)
{
    const int b    = blockIdx.x;
    const int tid  = threadIdx.x;
    const int lane = tid & 31;
    const int wid  = tid >> 5;

    __shared__ float u_s[DD];
    __shared__ float red[16];
    __shared__ float s_vb, s_pos;

    // stage u[b] into smem; accumulate partials for vb-dot and pos-dot
    float pv = 0.f, pp = 0.f;
    #pragma unroll
    for (int i = tid * 4; i < DD; i += 1024) {
        float4 u4 = *reinterpret_cast<const float4*>(&g_u[b * DD + i]);
        *reinterpret_cast<float4*>(&u_s[i]) = u4;
        float4 e4 = *reinterpret_cast<const float4*>(&E[b * DD + i]);
        float4 v4 = *reinterpret_cast<const float4*>(&vb[i]);
        float4 c4 = *reinterpret_cast<const float4*>(&cand[b * DD + i]);
        pv += e4.x * v4.x + e4.y * v4.y + e4.z * v4.z + e4.w * v4.w;
        pp += u4.x * c4.x + u4.y * c4.y + u4.z * c4.z + u4.w * c4.w;
    }
    #pragma unroll
    for (int o = 16; o > 0; o >>= 1) {
        pv += __shfl_xor_sync(0xFFFFFFFFu, pv, o);
        pp += __shfl_xor_sync(0xFFFFFFFFu, pp, o);
    }
    if (lane == 0) { red[wid] = pv; red[8 + wid] = pp; }
    __syncthreads();
    if (tid == 0) {
        float v = 0.f, p = 0.f;
        #pragma unroll
        for (int w = 0; w < 8; w++) { v += red[w]; p += red[8 + w]; }
        s_vb  = v;
        s_pos = p + v;
    }
    __syncthreads();
    const float vbb = s_vb;

    // negative phase: warp w handles theo rows w, w+8, ...
    const float4* u4p = reinterpret_cast<const float4*>(u_s);
    for (int t = wid; t < TT; t += 8) {
        const float4* tr =
            reinterpret_cast<const float4*>(&theo[((size_t)b * TT + t) * DD]);
        float s = 0.f;
        #pragma unroll 4
        for (int i = lane; i < DD / 4; i += 32) {
            float4 t4 = tr[i];
            float4 u4 = u4p[i];
            s += t4.x * u4.x + t4.y * u4.y + t4.z * u4.z + t4.w * u4.w;
        }
        #pragma unroll
        for (int o = 16; o > 0; o >>= 1) s += __shfl_xor_sync(0xFFFFFFFFu, s, o);
        if (lane == 0) out[b * (TT + 1) + 1 + t] = s + vbb;
    }
    if (tid == 0) out[b * (TT + 1)] = s_pos;
}

// ---------------------------------------------------------------------------
// launch
// inputs: 0=experimental [B,D], 1=theoretical [B,T,D], 2=candidate [B,D],
//         3=W [D,D], 4=vb [D], 5=hb [D]; out: [B, 1+T] fp32
// ---------------------------------------------------------------------------
extern "C" void kernel_launch(void* const* d_in, const int* in_sizes, int n_in,
                              void* d_out, int out_size)
{
    const float* E    = (const float*)d_in[0];
    const float* theo = (const float*)d_in[1];
    const float* cand = (const float*)d_in[2];
    const float* W    = (const float*)d_in[3];
    const float* vb   = (const float*)d_in[4];
    const float* hb   = (const float*)d_in[5];
    float*       out  = (float*)d_out;

    dim3 gridA(DD / 64, BB / 64);   // (32, 4)
    gemm_u_kernel<<<gridA, 256>>>(E, W, hb);
    score_kernel<<<BB, 256>>>(E, theo, cand, vb, out);
}

// round 2
// speedup vs baseline: 2.8203x; 2.8203x over previous
#include <cuda_runtime.h>
#include <cuda_bf16.h>
#include <cstdint>

#define DD 2048
#define BB 256
#define TT 64

// scratch (static device arrays — no allocations)
__device__ float          g_u [BB * DD];   // 2 MB: u = E@(W-I) + E + hb
__device__ __nv_bfloat16  g_Eh[BB * DD];   // 1 MB
__device__ __nv_bfloat16  g_Wh[DD * DD];   // 8 MB: bf16(W - I)

// ---------------------------------------------------------------------------
// Kernel 0: convert E -> bf16, (W - I) -> bf16
// ---------------------------------------------------------------------------
__global__ __launch_bounds__(256) void convert_kernel(
    const float* __restrict__ E, const float* __restrict__ W)
{
    const int NW = DD * DD / 4;
    const int NE = BB * DD / 4;
    int idx = blockIdx.x * 256 + threadIdx.x;
    if (idx < NW) {
        float4 v = reinterpret_cast<const float4*>(W)[idx];
        int base = idx << 2;
        int r = base >> 11;            // row (k)
        int d = r - (base & (DD - 1)); // diag offset within this float4
        if (d >= 0 && d < 4) reinterpret_cast<float*>(&v)[d] -= 1.0f;
        __nv_bfloat162* o = reinterpret_cast<__nv_bfloat162*>(g_Wh) + idx * 2;
        o[0] = __nv_bfloat162(__float2bfloat16_rn(v.x), __float2bfloat16_rn(v.y));
        o[1] = __nv_bfloat162(__float2bfloat16_rn(v.z), __float2bfloat16_rn(v.w));
    } else if (idx < NW + NE) {
        int j = idx - NW;
        float4 v = reinterpret_cast<const float4*>(E)[j];
        __nv_bfloat162* o = reinterpret_cast<__nv_bfloat162*>(g_Eh) + j * 2;
        o[0] = __nv_bfloat162(__float2bfloat16_rn(v.x), __float2bfloat16_rn(v.y));
        o[1] = __nv_bfloat162(__float2bfloat16_rn(v.z), __float2bfloat16_rn(v.w));
    }
}

// ---------------------------------------------------------------------------
// Kernel A: tensor-core GEMM  U = Eh @ Wh + E + hb
// BM=BN=BK=64, 256 threads (8 warps, 2x4), warp tile 32x16, mma.m16n8k16 bf16
// double-buffered cp.async, XOR-swizzled smem (128B rows, conflict-free ldmatrix)
// ---------------------------------------------------------------------------
__device__ __forceinline__ void mma16816(float* d, const uint32_t* a,
                                         uint32_t b0, uint32_t b1)
{
    asm volatile(
        "mma.sync.aligned.m16n8k16.row.col.f32.bf16.bf16.f32 "
        "{%0,%1,%2,%3}, {%4,%5,%6,%7}, {%8,%9}, {%0,%1,%2,%3};\n"
        : "+f"(d[0]), "+f"(d[1]), "+f"(d[2]), "+f"(d[3])
        : "r"(a[0]), "r"(a[1]), "r"(a[2]), "r"(a[3]), "r"(b0), "r"(b1));
}

__device__ __forceinline__ void ldsm_x4(uint32_t* r, uint32_t addr)
{
    asm volatile("ldmatrix.sync.aligned.m8n8.x4.shared.b16 {%0,%1,%2,%3}, [%4];\n"
                 : "=r"(r[0]), "=r"(r[1]), "=r"(r[2]), "=r"(r[3]) : "r"(addr));
}

__device__ __forceinline__ void ldsm_x4_t(uint32_t* r, uint32_t addr)
{
    asm volatile("ldmatrix.sync.aligned.m8n8.x4.trans.shared.b16 {%0,%1,%2,%3}, [%4];\n"
                 : "=r"(r[0]), "=r"(r[1]), "=r"(r[2]), "=r"(r[3]) : "r"(addr));
}

__device__ __forceinline__ void cp16(uint32_t saddr, const void* gaddr)
{
    asm volatile("cp.async.cg.shared.global [%0], [%1], 16;\n"
                 :: "r"(saddr), "l"(gaddr) : "memory");
}

__global__ __launch_bounds__(256) void gemm_u_kernel(
    const float* __restrict__ E, const float* __restrict__ hb)
{
    __shared__ __align__(1024) __nv_bfloat16 As[2][64 * 64];
    __shared__ __align__(1024) __nv_bfloat16 Bs[2][64 * 64];

    const int tid  = threadIdx.x;
    const int lane = tid & 31;
    const int wid  = tid >> 5;
    const int wm   = (wid >> 2) << 5;   // 0 / 32
    const int wn   = (wid & 3) << 4;    // 0,16,32,48
    const int bm   = blockIdx.y << 6;
    const int bn   = blockIdx.x << 6;

    float acc[2][2][4];
    #pragma unroll
    for (int i = 0; i < 2; i++)
        #pragma unroll
        for (int j = 0; j < 2; j++)
            #pragma unroll
            for (int k = 0; k < 4; k++) acc[i][j][k] = 0.f;

    // per-thread cp.async descriptors: chunks q=tid and q=tid+256
    const int r0 = tid >> 3;            // row 0..31 (second chunk: +32)
    const int c0 = tid & 7;             // 16B chunk within 128B row
    const uint32_t swzOff = (uint32_t)((r0 << 7) + (((c0 ^ (r0 & 7))) << 4));
    const uint32_t swzOff2 = swzOff + (32 << 7);  // (r0+32): same (r&7)

    uint32_t sA[2], sB[2];
    sA[0] = (uint32_t)__cvta_generic_to_shared(&As[0][0]);
    sA[1] = (uint32_t)__cvta_generic_to_shared(&As[1][0]);
    sB[0] = (uint32_t)__cvta_generic_to_shared(&Bs[0][0]);
    sB[1] = (uint32_t)__cvta_generic_to_shared(&Bs[1][0]);

    const __nv_bfloat16* gA  = g_Eh + (size_t)(bm + r0) * DD + c0 * 8;
    const __nv_bfloat16* gA2 = gA + (size_t)32 * DD;
    const __nv_bfloat16* gB  = g_Wh + (size_t)r0 * DD + bn + c0 * 8;
    const __nv_bfloat16* gB2 = gB + (size_t)32 * DD;

    // ldmatrix source offsets (per stage base + these)
    const int l15 = lane & 15;
    const int l7  = lane & 7;
    const int kcB = lane >> 4;          // 0/1: low/high 8-chunk
    uint32_t aRow[2];
    #pragma unroll
    for (int im = 0; im < 2; im++) aRow[im] = (uint32_t)((wm + im * 16 + l15) << 7);
    const uint32_t bRowBase = (uint32_t)(l15 << 7);   // + kk*16 rows
    const int nChunkBase = wn >> 3;

    #define LOAD_TILES(s, k0)                                              \
        {                                                                  \
            cp16(sA[s] + swzOff,  gA  + (k0));                             \
            cp16(sA[s] + swzOff2, gA2 + (k0));                             \
            cp16(sB[s] + swzOff,  gB  + (size_t)(k0) * DD);                \
            cp16(sB[s] + swzOff2, gB2 + (size_t)(k0) * DD);                \
            asm volatile("cp.async.commit_group;\n" ::: "memory");         \
        }

    LOAD_TILES(0, 0);

    const int NIT = DD / 64;   // 32
    for (int it = 0; it < NIT; it++) {
        const int s = it & 1;
        if (it + 1 < NIT) {
            LOAD_TILES(s ^ 1, (it + 1) * 64);
            asm volatile("cp.async.wait_group 1;\n" ::: "memory");
        } else {
            asm volatile("cp.async.wait_group 0;\n" ::: "memory");
        }
        __syncthreads();

        #pragma unroll
        for (int kk = 0; kk < 4; kk++) {
            uint32_t a[2][4], b[4];
            const int kchunk = kk * 2 + kcB;
            #pragma unroll
            for (int im = 0; im < 2; im++)
                ldsm_x4(a[im], sA[s] + aRow[im] + (uint32_t)(((kchunk ^ l7)) << 4));
            {
                const int krow = kk * 16 + l15;
                const int nchunk = nChunkBase + kcB;
                ldsm_x4_t(b, sB[s] + (uint32_t)(krow << 7)
                               + (uint32_t)(((nchunk ^ (krow & 7))) << 4));
            }
            #pragma unroll
            for (int im = 0; im < 2; im++) {
                mma16816(acc[im][0], a[im], b[0], b[1]);
                mma16816(acc[im][1], a[im], b[2], b[3]);
            }
        }
        __syncthreads();
    }
    #undef LOAD_TILES

    // epilogue: u = acc + E (exact identity part) + hb
    #pragma unroll
    for (int im = 0; im < 2; im++) {
        const int row0 = bm + wm + im * 16 + (lane >> 2);
        #pragma unroll
        for (int in = 0; in < 2; in++) {
            const int col = bn + wn + in * 8 + ((lane & 3) << 1);
            const float h0 = hb[col], h1 = hb[col + 1];
            g_u[(size_t)row0 * DD + col]
                = acc[im][in][0] + E[(size_t)row0 * DD + col] + h0;
            g_u[(size_t)row0 * DD + col + 1]
                = acc[im][in][1] + E[(size_t)row0 * DD + col + 1] + h1;
            g_u[(size_t)(row0 + 8) * DD + col]
                = acc[im][in][2] + E[(size_t)(row0 + 8) * DD + col] + h0;
            g_u[(size_t)(row0 + 8) * DD + col + 1]
                = acc[im][in][3] + E[(size_t)(row0 + 8) * DD + col + 1] + h1;
        }
    }
}

// ---------------------------------------------------------------------------
// Kernel B: scoring. grid (256, 4), 256 threads. CTA (b, tc) handles 16 t-rows;
// each warp does 2 rows with dual accumulators for MLP.
//   vb_b   = dot(E[b], vb)    (computed by every CTA — cheap, L2-resident)
//   pos    = dot(u[b], cand[b]) + vb_b      (candidate@hb cancels exactly)
//   neg[t] = dot(theo[b,t], u[b]) + vb_b
// ---------------------------------------------------------------------------
__global__ __launch_bounds__(256) void score_kernel(
    const float* __restrict__ E,
    const float* __restrict__ theo,
    const float* __restrict__ cand,
    const float* __restrict__ vb,
    float* __restrict__ out)
{
    const int b    = blockIdx.x;
    const int tc   = blockIdx.y;       // 0..3
    const int tid  = threadIdx.x;
    const int lane = tid & 31;
    const int wid  = tid >> 5;

    __shared__ float u_s[DD];
    __shared__ float red[16];
    __shared__ float s_vb, s_pos;

    float pv = 0.f, pp = 0.f;
    for (int i = tid * 4; i < DD; i += 1024) {
        float4 u4 = *reinterpret_cast<const float4*>(&g_u[(size_t)b * DD + i]);
        *reinterpret_cast<float4*>(&u_s[i]) = u4;
        float4 e4 = *reinterpret_cast<const float4*>(&E[(size_t)b * DD + i]);
        float4 v4 = *reinterpret_cast<const float4*>(&vb[i]);
        pv += e4.x * v4.x + e4.y * v4.y + e4.z * v4.z + e4.w * v4.w;
        if (tc == 0) {
            float4 c4 = *reinterpret_cast<const float4*>(&cand[(size_t)b * DD + i]);
            pp += u4.x * c4.x + u4.y * c4.y + u4.z * c4.z + u4.w * c4.w;
        }
    }
    #pragma unroll
    for (int o = 16; o > 0; o >>= 1) {
        pv += __shfl_xor_sync(0xFFFFFFFFu, pv, o);
        pp += __shfl_xor_sync(0xFFFFFFFFu, pp, o);
    }
    if (lane == 0) { red[wid] = pv; red[8 + wid] = pp; }
    __syncthreads();
    if (tid == 0) {
        float v = 0.f, p = 0.f;
        #pragma unroll
        for (int w = 0; w < 8; w++) { v += red[w]; p += red[8 + w]; }
        s_vb  = v;
        s_pos = p + v;
    }
    __syncthreads();
    const float vbb = s_vb;

    const int t0 = tc * 16 + wid * 2;
    const float4* ra  = reinterpret_cast<const float4*>(&theo[((size_t)b * TT + t0) * DD]);
    const float4* rb  = ra + DD / 4;
    const float4* u4p = reinterpret_cast<const float4*>(u_s);

    float s0 = 0.f, s1 = 0.f;
    #pragma unroll 4
    for (int i = lane; i < DD / 4; i += 32) {
        float4 x = ra[i];
        float4 y = rb[i];
        float4 u = u4p[i];
        s0 += x.x * u.x + x.y * u.y + x.z * u.z + x.w * u.w;
        s1 += y.x * u.x + y.y * u.y + y.z * u.z + y.w * u.w;
    }
    #pragma unroll
    for (int o = 16; o > 0; o >>= 1) {
        s0 += __shfl_xor_sync(0xFFFFFFFFu, s0, o);
        s1 += __shfl_xor_sync(0xFFFFFFFFu, s1, o);
    }
    if (lane == 0) {
        out[b * (TT + 1) + 1 + t0]     = s0 + vbb;
        out[b * (TT + 1) + 1 + t0 + 1] = s1 + vbb;
    }
    if (tc == 0 && tid == 0) out[b * (TT + 1)] = s_pos;
}

// ---------------------------------------------------------------------------
// launch: 0=experimental [B,D], 1=theoretical [B,T,D], 2=candidate [B,D],
//         3=W [D,D], 4=vb [D], 5=hb [D] ; out fp32 [B, 1+T]
// ---------------------------------------------------------------------------
extern "C" void kernel_launch(void* const* d_in, const int* in_sizes, int n_in,
                              void* d_out, int out_size)
{
    const float* E    = (const float*)d_in[0];
    const float* theo = (const float*)d_in[1];
    const float* cand = (const float*)d_in[2];
    const float* W    = (const float*)d_in[3];
    const float* vb   = (const float*)d_in[4];
    const float* hb   = (const float*)d_in[5];
    float*       out  = (float*)d_out;

    const int nconv = (DD * DD / 4 + BB * DD / 4 + 255) / 256;
    convert_kernel<<<nconv, 256>>>(E, W);
    gemm_u_kernel<<<dim3(DD / 64, BB / 64), 256>>>(E, hb);
    score_kernel<<<dim3(BB, 4), 256>>>(E, theo, cand, vb, out);
}

// round 3
// speedup vs baseline: 3.1810x; 1.1279x over previous
#include <cuda_runtime.h>
#include <cuda_bf16.h>
#include <cstdint>

#define DD 2048
#define BB 256
#define TT 64

// scratch (static device arrays — no allocations)
__device__ float          g_u [BB * DD];   // 2 MB: u = E@(W-I) + E + hb
__device__ __nv_bfloat16  g_Eh[BB * DD];   // 1 MB
__device__ __nv_bfloat16  g_Wh[DD * DD];   // 8 MB: bf16(W - I)

// ---------------------------------------------------------------------------
// Kernel 0: convert E -> bf16, (W - I) -> bf16.  4 float4 jobs per thread
// (MLP=4 hides DRAM latency).  Grid covers work exactly: (NW+NE)/1024 blocks.
// ---------------------------------------------------------------------------
__global__ __launch_bounds__(256) void convert_kernel(
    const float* __restrict__ E, const float* __restrict__ W)
{
    const int NW = DD * DD / 4;                 // 1048576 W float4s
    const int base = blockIdx.x * 1024 + threadIdx.x;

    int    idx[4];
    float4 v[4];
    #pragma unroll
    for (int x = 0; x < 4; x++) {
        idx[x] = base + x * 256;
        v[x] = (idx[x] < NW)
             ? reinterpret_cast<const float4*>(W)[idx[x]]
             : reinterpret_cast<const float4*>(E)[idx[x] - NW];
    }
    #pragma unroll
    for (int x = 0; x < 4; x++) {
        if (idx[x] < NW) {
            int fbase = idx[x] << 2;
            int r = fbase >> 11;                  // W row
            int d = r - (fbase & (DD - 1));       // diag offset in this float4
            if (d >= 0 && d < 4) reinterpret_cast<float*>(&v[x])[d] -= 1.0f;
            __nv_bfloat162 p0 = __floats2bfloat162_rn(v[x].x, v[x].y);
            __nv_bfloat162 p1 = __floats2bfloat162_rn(v[x].z, v[x].w);
            uint2 o; o.x = *reinterpret_cast<uint32_t*>(&p0);
                     o.y = *reinterpret_cast<uint32_t*>(&p1);
            reinterpret_cast<uint2*>(g_Wh)[idx[x]] = o;
        } else {
            int j = idx[x] - NW;
            __nv_bfloat162 p0 = __floats2bfloat162_rn(v[x].x, v[x].y);
            __nv_bfloat162 p1 = __floats2bfloat162_rn(v[x].z, v[x].w);
            uint2 o; o.x = *reinterpret_cast<uint32_t*>(&p0);
                     o.y = *reinterpret_cast<uint32_t*>(&p1);
            reinterpret_cast<uint2*>(g_Eh)[j] = o;
        }
    }
}

// ---------------------------------------------------------------------------
// Kernel A: tensor-core GEMM  U = Eh @ Wh + E + hb   (unchanged, validated)
// ---------------------------------------------------------------------------
__device__ __forceinline__ void mma16816(float* d, const uint32_t* a,
                                         uint32_t b0, uint32_t b1)
{
    asm volatile(
        "mma.sync.aligned.m16n8k16.row.col.f32.bf16.bf16.f32 "
        "{%0,%1,%2,%3}, {%4,%5,%6,%7}, {%8,%9}, {%0,%1,%2,%3};\n"
        : "+f"(d[0]), "+f"(d[1]), "+f"(d[2]), "+f"(d[3])
        : "r"(a[0]), "r"(a[1]), "r"(a[2]), "r"(a[3]), "r"(b0), "r"(b1));
}
__device__ __forceinline__ void ldsm_x4(uint32_t* r, uint32_t addr)
{
    asm volatile("ldmatrix.sync.aligned.m8n8.x4.shared.b16 {%0,%1,%2,%3}, [%4];\n"
                 : "=r"(r[0]), "=r"(r[1]), "=r"(r[2]), "=r"(r[3]) : "r"(addr));
}
__device__ __forceinline__ void ldsm_x4_t(uint32_t* r, uint32_t addr)
{
    asm volatile("ldmatrix.sync.aligned.m8n8.x4.trans.shared.b16 {%0,%1,%2,%3}, [%4];\n"
                 : "=r"(r[0]), "=r"(r[1]), "=r"(r[2]), "=r"(r[3]) : "r"(addr));
}
__device__ __forceinline__ void cp16(uint32_t saddr, const void* gaddr)
{
    asm volatile("cp.async.cg.shared.global [%0], [%1], 16;\n"
                 :: "r"(saddr), "l"(gaddr) : "memory");
}

__global__ __launch_bounds__(256) void gemm_u_kernel(
    const float* __restrict__ E, const float* __restrict__ hb)
{
    __shared__ __align__(1024) __nv_bfloat16 As[2][64 * 64];
    __shared__ __align__(1024) __nv_bfloat16 Bs[2][64 * 64];

    const int tid  = threadIdx.x;
    const int lane = tid & 31;
    const int wid  = tid >> 5;
    const int wm   = (wid >> 2) << 5;
    const int wn   = (wid & 3) << 4;
    const int bm   = blockIdx.y << 6;
    const int bn   = blockIdx.x << 6;

    float acc[2][2][4];
    #pragma unroll
    for (int i = 0; i < 2; i++)
        #pragma unroll
        for (int j = 0; j < 2; j++)
            #pragma unroll
            for (int k = 0; k < 4; k++) acc[i][j][k] = 0.f;

    const int r0 = tid >> 3;
    const int c0 = tid & 7;
    const uint32_t swzOff  = (uint32_t)((r0 << 7) + ((c0 ^ (r0 & 7)) << 4));
    const uint32_t swzOff2 = swzOff + (32 << 7);

    uint32_t sA[2], sB[2];
    sA[0] = (uint32_t)__cvta_generic_to_shared(&As[0][0]);
    sA[1] = (uint32_t)__cvta_generic_to_shared(&As[1][0]);
    sB[0] = (uint32_t)__cvta_generic_to_shared(&Bs[0][0]);
    sB[1] = (uint32_t)__cvta_generic_to_shared(&Bs[1][0]);

    const __nv_bfloat16* gA  = g_Eh + (size_t)(bm + r0) * DD + c0 * 8;
    const __nv_bfloat16* gA2 = gA + (size_t)32 * DD;
    const __nv_bfloat16* gB  = g_Wh + (size_t)r0 * DD + bn + c0 * 8;
    const __nv_bfloat16* gB2 = gB + (size_t)32 * DD;

    const int l15 = lane & 15;
    const int l7  = lane & 7;
    const int kcB = lane >> 4;
    uint32_t aRow[2];
    #pragma unroll
    for (int im = 0; im < 2; im++) aRow[im] = (uint32_t)((wm + im * 16 + l15) << 7);
    const int nChunkBase = wn >> 3;

    #define LOAD_TILES(s, k0)                                              \
        {                                                                  \
            cp16(sA[s] + swzOff,  gA  + (k0));                             \
            cp16(sA[s] + swzOff2, gA2 + (k0));                             \
            cp16(sB[s] + swzOff,  gB  + (size_t)(k0) * DD);                \
            cp16(sB[s] + swzOff2, gB2 + (size_t)(k0) * DD);                \
            asm volatile("cp.async.commit_group;\n" ::: "memory");         \
        }

    LOAD_TILES(0, 0);

    const int NIT = DD / 64;
    for (int it = 0; it < NIT; it++) {
        const int s = it & 1;
        if (it + 1 < NIT) {
            LOAD_TILES(s ^ 1, (it + 1) * 64);
            asm volatile("cp.async.wait_group 1;\n" ::: "memory");
        } else {
            asm volatile("cp.async.wait_group 0;\n" ::: "memory");
        }
        __syncthreads();

        #pragma unroll
        for (int kk = 0; kk < 4; kk++) {
            uint32_t a[2][4], b[4];
            const int kchunk = kk * 2 + kcB;
            #pragma unroll
            for (int im = 0; im < 2; im++)
                ldsm_x4(a[im], sA[s] + aRow[im] + (uint32_t)((kchunk ^ l7) << 4));
            {
                const int krow = kk * 16 + l15;
                const int nchunk = nChunkBase + kcB;
                ldsm_x4_t(b, sB[s] + (uint32_t)(krow << 7)
                               + (uint32_t)((nchunk ^ (krow & 7)) << 4));
            }
            #pragma unroll
            for (int im = 0; im < 2; im++) {
                mma16816(acc[im][0], a[im], b[0], b[1]);
                mma16816(acc[im][1], a[im], b[2], b[3]);
            }
        }
        __syncthreads();
    }
    #undef LOAD_TILES

    #pragma unroll
    for (int im = 0; im < 2; im++) {
        const int row0 = bm + wm + im * 16 + (lane >> 2);
        #pragma unroll
        for (int in = 0; in < 2; in++) {
            const int col = bn + wn + in * 8 + ((lane & 3) << 1);
            const float h0 = hb[col], h1 = hb[col + 1];
            g_u[(size_t)row0 * DD + col]
                = acc[im][in][0] + E[(size_t)row0 * DD + col] + h0;
            g_u[(size_t)row0 * DD + col + 1]
                = acc[im][in][1] + E[(size_t)row0 * DD + col + 1] + h1;
            g_u[(size_t)(row0 + 8) * DD + col]
                = acc[im][in][2] + E[(size_t)(row0 + 8) * DD + col] + h0;
            g_u[(size_t)(row0 + 8) * DD + col + 1]
                = acc[im][in][3] + E[(size_t)(row0 + 8) * DD + col + 1] + h1;
        }
    }
}

// ---------------------------------------------------------------------------
// Kernel B: scoring. grid (256, 2), 512 threads (16 warps). CTA (b, tc)
// covers 32 t-rows; warp w -> rows tc*32 + w*2 (+1). __ldcs on theo stream.
//   vb_b   = dot(E[b], vb) ;  pos = dot(u[b], cand[b]) + vb_b
//   neg[t] = dot(theo[b,t], u[b]) + vb_b
// ---------------------------------------------------------------------------
__global__ __launch_bounds__(512) void score_kernel(
    const float* __restrict__ E,
    const float* __restrict__ theo,
    const float* __restrict__ cand,
    const float* __restrict__ vb,
    float* __restrict__ out)
{
    const int b    = blockIdx.x;
    const int tc   = blockIdx.y;       // 0..1
    const int tid  = threadIdx.x;
    const int lane = tid & 31;
    const int wid  = tid >> 5;         // 0..15

    __shared__ float u_s[DD];
    __shared__ float red[32];
    __shared__ float s_vb, s_pos;

    // stage u[b]; one float4 per thread (512*4 = 2048 exactly)
    float pv, pp = 0.f;
    {
        const int i = tid * 4;
        float4 u4 = *reinterpret_cast<const float4*>(&g_u[(size_t)b * DD + i]);
        *reinterpret_cast<float4*>(&u_s[i]) = u4;
        float4 e4 = *reinterpret_cast<const float4*>(&E[(size_t)b * DD + i]);
        float4 v4 = *reinterpret_cast<const float4*>(&vb[i]);
        pv = e4.x * v4.x + e4.y * v4.y + e4.z * v4.z + e4.w * v4.w;
        if (tc == 0) {
            float4 c4 = *reinterpret_cast<const float4*>(&cand[(size_t)b * DD + i]);
            pp = u4.x * c4.x + u4.y * c4.y + u4.z * c4.z + u4.w * c4.w;
        }
    }
    #pragma unroll
    for (int o = 16; o > 0; o >>= 1) {
        pv += __shfl_xor_sync(0xFFFFFFFFu, pv, o);
        pp += __shfl_xor_sync(0xFFFFFFFFu, pp, o);
    }
    if (lane == 0) { red[wid] = pv; red[16 + wid] = pp; }
    __syncthreads();
    if (tid == 0) {
        float v = 0.f, p = 0.f;
        #pragma unroll
        for (int w = 0; w < 16; w++) { v += red[w]; p += red[16 + w]; }
        s_vb  = v;
        s_pos = p + v;
    }
    __syncthreads();
    const float vbb = s_vb;

    const int t0 = tc * 32 + wid * 2;
    const float4* ra  = reinterpret_cast<const float4*>(&theo[((size_t)b * TT + t0) * DD]);
    const float4* rb  = ra + DD / 4;
    const float4* u4p = reinterpret_cast<const float4*>(u_s);

    float s0 = 0.f, s1 = 0.f;
    #pragma unroll 4
    for (int i = lane; i < DD / 4; i += 32) {
        float4 x = __ldcs(&ra[i]);
        float4 y = __ldcs(&rb[i]);
        float4 u = u4p[i];
        s0 += x.x * u.x + x.y * u.y + x.z * u.z + x.w * u.w;
        s1 += y.x * u.x + y.y * u.y + y.z * u.z + y.w * u.w;
    }
    #pragma unroll
    for (int o = 16; o > 0; o >>= 1) {
        s0 += __shfl_xor_sync(0xFFFFFFFFu, s0, o);
        s1 += __shfl_xor_sync(0xFFFFFFFFu, s1, o);
    }
    if (lane == 0) {
        out[b * (TT + 1) + 1 + t0]     = s0 + vbb;
        out[b * (TT + 1) + 1 + t0 + 1] = s1 + vbb;
    }
    if (tc == 0 && tid == 0) out[b * (TT + 1)] = s_pos;
}

// ---------------------------------------------------------------------------
// launch: 0=experimental [B,D], 1=theoretical [B,T,D], 2=candidate [B,D],
//         3=W [D,D], 4=vb [D], 5=hb [D] ; out fp32 [B, 1+T]
// ---------------------------------------------------------------------------
extern "C" void kernel_launch(void* const* d_in, const int* in_sizes, int n_in,
                              void* d_out, int out_size)
{
    const float* E    = (const float*)d_in[0];
    const float* theo = (const float*)d_in[1];
    const float* cand = (const float*)d_in[2];
    const float* W    = (const float*)d_in[3];
    const float* vb   = (const float*)d_in[4];
    const float* hb   = (const float*)d_in[5];
    float*       out  = (float*)d_out;

    const int njobs  = DD * DD / 4 + BB * DD / 4;   // float4 jobs
    convert_kernel<<<njobs / 1024, 256>>>(E, W);
    gemm_u_kernel<<<dim3(DD / 64, BB / 64), 256>>>(E, hb);
    score_kernel<<<dim3(BB, 2), 512>>>(E, theo, cand, vb, out);
}